// round 1
// baseline (speedup 1.0000x reference)
#include <cuda_runtime.h>

// Problem constants
#define Bn   16
#define Tn   512
#define Fn   32
#define CIn  128
#define COn  128
#define Kn   3
#define DILn 2

// GEMM tiling
#define BM 64      // time rows per block
#define BN 128     // output channels per block
#define BK 16      // K-chunk (within one tap's CI)
#define TM 4       // per-thread rows
#define TN 8       // per-thread cols
#define NTHREADS 256

// Scratch: transposed weights wT[f][k][i][o]  (32*3*128*128 floats = 6.29 MB)
__device__ float g_wT[Fn * Kn * CIn * COn];

// ---------------------------------------------------------------------------
// One-time (per launch) weight transpose: w[f][o][i][k] -> wT[f][k][i][o]
// Writes are fully coalesced over o.
// ---------------------------------------------------------------------------
__global__ void transpose_w_kernel(const float* __restrict__ w) {
    int idx = blockIdx.x * blockDim.x + threadIdx.x;
    const int total = Fn * Kn * CIn * COn;
    if (idx >= total) return;
    int o = idx % COn;
    int i = (idx / COn) % CIn;
    int k = (idx / (COn * CIn)) % Kn;
    int f = idx / (COn * CIn * Kn);
    g_wT[idx] = w[((f * COn + o) * CIn + i) * Kn + k];
}

// ---------------------------------------------------------------------------
// Main conv kernel: block = (64 t) x (128 o) tile for fixed (b, f).
// y[b,t,f,o] = bias[f,o] + sum_{k,i} x[b, t-4+2k, f, i] * wT[f,k,i,o]
// ---------------------------------------------------------------------------
__global__ __launch_bounds__(NTHREADS)
void conv_gemm_kernel(const float* __restrict__ x,
                      const float* __restrict__ bias,
                      float* __restrict__ y) {
    __shared__ float As[BK][BM];   // A tile transposed: As[kidx][t]
    __shared__ float Bs[BK][BN];   // B tile: Bs[kidx][o]

    const int t0 = blockIdx.x * BM;      // time tile base
    const int f  = blockIdx.y;           // feature
    const int b  = blockIdx.z;           // batch

    const int tid = threadIdx.x;
    const int tr  = tid / 16;            // thread row  (0..15) -> t = tr*TM..
    const int tc  = tid % 16;            // thread col  (0..15) -> o = tc*TN..

    // A-tile load mapping: one float4 per thread per chunk
    const int a_row  = tid / 4;          // t within tile (0..63)
    const int a_quad = tid % 4;          // 4-float group within the 16-wide chunk

    // B-tile load mapping: two float4 per thread per chunk
    const int b_row  = tid / 32;         // 0..7  (and +8 for second)
    const int b_qcol = tid % 32;         // float4 column 0..31

    // Accumulators initialized with bias
    float acc[TM][TN];
    #pragma unroll
    for (int j = 0; j < TN; j++) {
        float bv = bias[f * COn + tc * TN + j];
        #pragma unroll
        for (int i2 = 0; i2 < TM; i2++) acc[i2][j] = bv;
    }

    // Base pointer for x rows of this (b, f): x[((b*T + t)*F + f)*CI + i]
    const long long x_row_stride = (long long)Fn * CIn;             // 4096 floats
    const float* xb = x + ((long long)b * Tn * Fn + f) * CIn;       // + t*4096 + i

    // K loop: taps (3) x ci chunks (128/16 = 8)  => 24 chunks
    for (int ktap = 0; ktap < Kn; ktap++) {
        const int tshift = -DILn * (Kn - 1) + DILn * ktap;          // -4, -2, 0
        const float* wTf = g_wT + ((long long)(f * Kn + ktap) * CIn) * COn;

        for (int i0 = 0; i0 < CIn; i0 += BK) {
            // ---- load A tile (64 x 16) ----
            {
                const int tg = t0 + a_row + tshift;                 // global t (may be < 0)
                float4 v = make_float4(0.f, 0.f, 0.f, 0.f);
                if (tg >= 0) {
                    v = *reinterpret_cast<const float4*>(
                        xb + (long long)tg * x_row_stride + i0 + a_quad * 4);
                }
                As[a_quad * 4 + 0][a_row] = v.x;
                As[a_quad * 4 + 1][a_row] = v.y;
                As[a_quad * 4 + 2][a_row] = v.z;
                As[a_quad * 4 + 3][a_row] = v.w;
            }
            // ---- load B tile (16 x 128) ----
            {
                const float4* src0 = reinterpret_cast<const float4*>(
                    wTf + (long long)(i0 + b_row) * COn) + b_qcol;
                const float4* src1 = reinterpret_cast<const float4*>(
                    wTf + (long long)(i0 + b_row + 8) * COn) + b_qcol;
                *reinterpret_cast<float4*>(&Bs[b_row][b_qcol * 4])     = *src0;
                *reinterpret_cast<float4*>(&Bs[b_row + 8][b_qcol * 4]) = *src1;
            }
            __syncthreads();

            // ---- compute 16 k-steps ----
            #pragma unroll
            for (int kk = 0; kk < BK; kk++) {
                float4 a4 = *reinterpret_cast<const float4*>(&As[kk][tr * TM]);
                float4 b0 = *reinterpret_cast<const float4*>(&Bs[kk][tc * TN]);
                float4 b1 = *reinterpret_cast<const float4*>(&Bs[kk][tc * TN + 4]);
                const float av[TM] = {a4.x, a4.y, a4.z, a4.w};
                const float bv[TN] = {b0.x, b0.y, b0.z, b0.w, b1.x, b1.y, b1.z, b1.w};
                #pragma unroll
                for (int i2 = 0; i2 < TM; i2++)
                    #pragma unroll
                    for (int j = 0; j < TN; j++)
                        acc[i2][j] = fmaf(av[i2], bv[j], acc[i2][j]);
            }
            __syncthreads();
        }
    }

    // ---- write out: y[((b*T + t)*F + f)*CO + o] ----
    #pragma unroll
    for (int i2 = 0; i2 < TM; i2++) {
        const int t = t0 + tr * TM + i2;
        float* yrow = y + ((long long)(b * Tn + t) * Fn + f) * COn + tc * TN;
        float4 v0 = make_float4(acc[i2][0], acc[i2][1], acc[i2][2], acc[i2][3]);
        float4 v1 = make_float4(acc[i2][4], acc[i2][5], acc[i2][6], acc[i2][7]);
        *reinterpret_cast<float4*>(yrow)     = v0;
        *reinterpret_cast<float4*>(yrow + 4) = v1;
    }
}

// ---------------------------------------------------------------------------
// Launch
// ---------------------------------------------------------------------------
extern "C" void kernel_launch(void* const* d_in, const int* in_sizes, int n_in,
                              void* d_out, int out_size) {
    const float* x    = (const float*)d_in[0];  // [B, T, F, CI]
    const float* w    = (const float*)d_in[1];  // [F, CO, CI, K]
    const float* bias = (const float*)d_in[2];  // [F, CO]
    float* y = (float*)d_out;                   // [B, T, F, CO]

    (void)in_sizes; (void)n_in; (void)out_size;

    // 1) transpose weights into scratch
    {
        const int total = Fn * Kn * CIn * COn;
        int threads = 256;
        int blocks = (total + threads - 1) / threads;
        transpose_w_kernel<<<blocks, threads>>>(w);
    }

    // 2) main conv-as-GEMM
    {
        dim3 grid(Tn / BM, Fn, Bn);  // (8, 32, 16) = 4096 blocks
        conv_gemm_kernel<<<grid, NTHREADS>>>(x, bias, y);
    }
}

// round 3
// speedup vs baseline: 5.9927x; 5.9927x over previous
#include <cuda_runtime.h>
#include <cstdint>

// Problem constants
#define Bn   16
#define Tn   512
#define Fn   32
#define CIn  128
#define COn  128
#define Kn   3
#define DILn 2

#define TILE_M   128
#define CHUNK    32            // K floats per chunk = 128B row
#define NCHUNKS  12            // 3 taps * 4
#define NTHREADS 128           // 4 warps, 64x64 warp tiles (2x2 grid)
#define NSTAGES  3

#define STAGE_BYTES 32768      // A 16KB + B 16KB
#define DYN_SMEM (NSTAGES * STAGE_BYTES)

#define SWZ128(off) ((off) ^ (((off) >> 3) & 0x70))

// Weights rearranged to wB[f][tap][o][ci], pre-rounded to tf32
__device__ float g_wB[Fn * Kn * COn * CIn];

// ---------------------------------------------------------------------------
__global__ void prep_w(const float* __restrict__ w) {
    int idx = blockIdx.x * blockDim.x + threadIdx.x;
    const int total = Fn * Kn * COn * CIn;
    if (idx >= total) return;
    int i = idx % CIn;
    int o = (idx / CIn) % COn;
    int k = (idx / (CIn * COn)) % Kn;
    int f = idx / (CIn * COn * Kn);
    float v = w[((f * COn + o) * CIn + i) * Kn + k];
    uint32_t t;
    asm("cvt.rna.tf32.f32 %0, %1;" : "=r"(t) : "f"(v));
    g_wB[idx] = __uint_as_float(t);
}

// ---------------------------------------------------------------------------
__device__ __forceinline__ uint32_t smem_u32(const void* p) {
    uint32_t a;
    asm("{ .reg .u64 t; cvta.to.shared.u64 t, %1; cvt.u32.u64 %0, t; }" : "=r"(a) : "l"(p));
    return a;
}
__device__ __forceinline__ void cp16(uint32_t saddr, const void* gaddr, uint32_t srcsize) {
    asm volatile("cp.async.cg.shared.global [%0], [%1], 16, %2;"
                 :: "r"(saddr), "l"(gaddr), "r"(srcsize));
}
__device__ __forceinline__ void ldsm_x4(uint32_t& r0, uint32_t& r1, uint32_t& r2, uint32_t& r3,
                                        uint32_t addr) {
    asm volatile("ldmatrix.sync.aligned.m8n8.x4.shared.b16 {%0,%1,%2,%3}, [%4];"
                 : "=r"(r0), "=r"(r1), "=r"(r2), "=r"(r3) : "r"(addr));
}
__device__ __forceinline__ uint32_t f2tf32(uint32_t x) {
    uint32_t r;
    asm("cvt.rna.tf32.f32 %0, %1;" : "=r"(r) : "f"(__uint_as_float(x)));
    return r;
}
__device__ __forceinline__ void mma_tf32(float* c, const uint32_t* a, const uint32_t* b) {
    asm volatile(
        "mma.sync.aligned.m16n8k8.row.col.f32.tf32.tf32.f32 "
        "{%0,%1,%2,%3}, {%4,%5,%6,%7}, {%8,%9}, {%0,%1,%2,%3};"
        : "+f"(c[0]), "+f"(c[1]), "+f"(c[2]), "+f"(c[3])
        : "r"(a[0]), "r"(a[1]), "r"(a[2]), "r"(a[3]), "r"(b[0]), "r"(b[1]));
}

// ---------------------------------------------------------------------------
// CTA = 128 t-rows x 128 CO for one (b, f). 4 warps, warp tile 64x64.
// ---------------------------------------------------------------------------
__global__ __launch_bounds__(NTHREADS)
void conv_mma_kernel(const float* __restrict__ x,
                     const float* __restrict__ bias,
                     float* __restrict__ y) {
    extern __shared__ char dsm[];
    __shared__ float s_bias[COn];

    const int t0 = blockIdx.x * TILE_M;
    const int f  = blockIdx.y;
    const int b  = blockIdx.z;
    const int tid = threadIdx.x;
    const int wid = tid >> 5;
    const int lane = tid & 31;
    const int wm = (wid >> 1) * 64;      // warp M base
    const int wn = (wid & 1) * 64;       // warp N base

    const uint32_t smb = smem_u32(dsm);

    const float* xb = x + ((long long)b * Tn * Fn + f) * CIn;   // + t*4096 + ci
    const float* wf = g_wB + (long long)f * Kn * COn * CIn;     // + tap*16384 + o*128 + ci

    if (tid < COn) s_bias[tid] = bias[f * COn + tid];

    // ---- loader lambda: chunk c -> stage s ----
    const int lrow8 = tid >> 3;          // 0..15
    const int lcol  = tid & 7;           // 16B column
    auto load_chunk = [&](int c, int s) {
        const int ktap = c >> 2;
        const int ci0  = (c & 3) * CHUNK;
        const int tshift = -DILn * (Kn - 1) + DILn * ktap;      // -4,-2,0
        const uint32_t Ab = smb + s * STAGE_BYTES;
        const uint32_t Bb = Ab + 16384;
        #pragma unroll
        for (int p = 0; p < 8; p++) {
            const int row = p * 16 + lrow8;
            // A
            const int tg = t0 + row + tshift;
            const float* ga = (tg >= 0) ? xb + (long long)tg * (Fn * CIn) + ci0 + lcol * 4
                                        : xb;
            cp16(Ab + SWZ128(row * 128 + lcol * 16), ga, (tg >= 0) ? 16u : 0u);
            // B
            const float* gb = wf + (long long)ktap * (COn * CIn) + (long long)row * CIn
                              + ci0 + lcol * 4;
            cp16(Bb + SWZ128(row * 128 + lcol * 16), gb, 16u);
        }
    };

    // ---- prologue ----
    load_chunk(0, 0);
    asm volatile("cp.async.commit_group;");
    load_chunk(1, 1);
    asm volatile("cp.async.commit_group;");

    __syncthreads();   // s_bias ready

    // ---- accumulators (init with bias) ----
    float acc[4][8][4];
    #pragma unroll
    for (int nf = 0; nf < 8; nf++) {
        const int n = wn + nf * 8 + (lane & 3) * 2;
        const float b0 = s_bias[n], b1 = s_bias[n + 1];
        #pragma unroll
        for (int mf = 0; mf < 4; mf++) {
            acc[mf][nf][0] = b0; acc[mf][nf][1] = b1;
            acc[mf][nf][2] = b0; acc[mf][nf][3] = b1;
        }
    }

    // ldmatrix lane addressing
    const int a_row = wm + (lane & 15);
    const int a_cb  = (lane >> 4) << 4;                  // 0 or 16
    const int b_row = wn + (lane & 7) + ((lane >> 4) << 3);
    const int b_cb  = ((lane >> 3) & 1) * 16;

    // ---- main loop ----
    #pragma unroll 1
    for (int c = 0; c < NCHUNKS; c++) {
        const int s = c % NSTAGES;
        asm volatile("cp.async.wait_group 1;");
        __syncthreads();

        if (c + 2 < NCHUNKS) load_chunk(c + 2, (c + 2) % NSTAGES);
        asm volatile("cp.async.commit_group;");

        const uint32_t Ab = smb + s * STAGE_BYTES;
        const uint32_t Bb = Ab + 16384;

        #pragma unroll
        for (int ks = 0; ks < 4; ks++) {
            uint32_t afr[4][4], bfr[8][2];
            #pragma unroll
            for (int mf = 0; mf < 4; mf++) {
                ldsm_x4(afr[mf][0], afr[mf][1], afr[mf][2], afr[mf][3],
                        Ab + SWZ128((a_row + mf * 16) * 128 + ks * 32 + a_cb));
                afr[mf][0] = f2tf32(afr[mf][0]);
                afr[mf][1] = f2tf32(afr[mf][1]);
                afr[mf][2] = f2tf32(afr[mf][2]);
                afr[mf][3] = f2tf32(afr[mf][3]);
            }
            #pragma unroll
            for (int nf2 = 0; nf2 < 4; nf2++) {
                uint32_t r0, r1, r2, r3;
                ldsm_x4(r0, r1, r2, r3,
                        Bb + SWZ128((b_row + nf2 * 16) * 128 + ks * 32 + b_cb));
                bfr[nf2 * 2][0] = r0;     bfr[nf2 * 2][1] = r1;
                bfr[nf2 * 2 + 1][0] = r2; bfr[nf2 * 2 + 1][1] = r3;
            }
            #pragma unroll
            for (int mf = 0; mf < 4; mf++)
                #pragma unroll
                for (int nf = 0; nf < 8; nf++)
                    mma_tf32(acc[mf][nf], afr[mf], bfr[nf]);
        }
    }

    // ---- epilogue ----
    #pragma unroll
    for (int mf = 0; mf < 4; mf++) {
        #pragma unroll
        for (int r2 = 0; r2 < 2; r2++) {
            const int t = t0 + wm + mf * 16 + (lane >> 2) + r2 * 8;
            float* yrow = y + ((long long)(b * Tn + t) * Fn + f) * COn;
            #pragma unroll
            for (int nf = 0; nf < 8; nf++) {
                const int n = wn + nf * 8 + (lane & 3) * 2;
                float2 v = make_float2(acc[mf][nf][r2 * 2], acc[mf][nf][r2 * 2 + 1]);
                *reinterpret_cast<float2*>(yrow + n) = v;
            }
        }
    }
}

// ---------------------------------------------------------------------------
extern "C" void kernel_launch(void* const* d_in, const int* in_sizes, int n_in,
                              void* d_out, int out_size) {
    const float* x    = (const float*)d_in[0];  // [B, T, F, CI]
    const float* w    = (const float*)d_in[1];  // [F, CO, CI, K]
    const float* bias = (const float*)d_in[2];  // [F, CO]
    float* y = (float*)d_out;                   // [B, T, F, CO]
    (void)in_sizes; (void)n_in; (void)out_size;

    {
        const int total = Fn * Kn * COn * CIn;
        prep_w<<<(total + 255) / 256, 256>>>(w);
    }
    {
        static bool attr_set = false;
        if (!attr_set) {
            cudaFuncSetAttribute(conv_mma_kernel,
                                 cudaFuncAttributeMaxDynamicSharedMemorySize, DYN_SMEM);
            attr_set = true;
        }
        dim3 grid(Tn / TILE_M, Fn, Bn);   // (4, 32, 16) = 2048 CTAs
        conv_mma_kernel<<<grid, NTHREADS, DYN_SMEM>>>(x, bias, y);
    }
}

// round 4
// speedup vs baseline: 6.6271x; 1.1059x over previous
#include <cuda_runtime.h>
#include <cstdint>

// Problem constants
#define Bn   16
#define Tn   512
#define Fn   32
#define CIn  128
#define COn  128
#define Kn   3
#define DILn 2

#define TILE_M   128
#define CHUNK    32            // K floats per chunk = 128B row
#define NCHUNKS  12            // 3 taps * 4
#define NTHREADS 256           // 8 warps, 32x64 warp tiles (4x2 grid)
#define NSTAGES  2

#define STAGE_BYTES 32768      // A 16KB + B 16KB
#define DYN_SMEM (NSTAGES * STAGE_BYTES)

#define SWZ128(off) ((off) ^ (((off) >> 3) & 0x70))

// Weights rearranged to wB[f][tap][o][ci], pre-rounded to tf32
__device__ float g_wB[Fn * Kn * COn * CIn];

// ---------------------------------------------------------------------------
__global__ void prep_w(const float* __restrict__ w) {
    int idx = blockIdx.x * blockDim.x + threadIdx.x;
    const int total = Fn * Kn * COn * CIn;
    if (idx >= total) return;
    int i = idx % CIn;
    int o = (idx / CIn) % COn;
    int k = (idx / (CIn * COn)) % Kn;
    int f = idx / (CIn * COn * Kn);
    float v = w[((f * COn + o) * CIn + i) * Kn + k];
    uint32_t t;
    asm("cvt.rna.tf32.f32 %0, %1;" : "=r"(t) : "f"(v));
    g_wB[idx] = __uint_as_float(t);
}

// ---------------------------------------------------------------------------
__device__ __forceinline__ uint32_t smem_u32(const void* p) {
    uint32_t a;
    asm("{ .reg .u64 t; cvta.to.shared.u64 t, %1; cvt.u32.u64 %0, t; }" : "=r"(a) : "l"(p));
    return a;
}
__device__ __forceinline__ void cp16(uint32_t saddr, const void* gaddr, uint32_t srcsize) {
    asm volatile("cp.async.cg.shared.global [%0], [%1], 16, %2;"
                 :: "r"(saddr), "l"(gaddr), "r"(srcsize));
}
__device__ __forceinline__ void ldsm_x4(uint32_t& r0, uint32_t& r1, uint32_t& r2, uint32_t& r3,
                                        uint32_t addr) {
    asm volatile("ldmatrix.sync.aligned.m8n8.x4.shared.b16 {%0,%1,%2,%3}, [%4];"
                 : "=r"(r0), "=r"(r1), "=r"(r2), "=r"(r3) : "r"(addr));
}
__device__ __forceinline__ void mma_tf32(float* c, const uint32_t* a, const uint32_t* b) {
    asm volatile(
        "mma.sync.aligned.m16n8k8.row.col.f32.tf32.tf32.f32 "
        "{%0,%1,%2,%3}, {%4,%5,%6,%7}, {%8,%9}, {%0,%1,%2,%3};"
        : "+f"(c[0]), "+f"(c[1]), "+f"(c[2]), "+f"(c[3])
        : "r"(a[0]), "r"(a[1]), "r"(a[2]), "r"(a[3]), "r"(b[0]), "r"(b[1]));
}

// ---------------------------------------------------------------------------
// CTA = 128 t-rows x 128 CO for one (b, f). 8 warps, warp tile 32x64.
// ---------------------------------------------------------------------------
__global__ __launch_bounds__(NTHREADS, 2)
void conv_mma_kernel(const float* __restrict__ x,
                     const float* __restrict__ bias,
                     float* __restrict__ y) {
    extern __shared__ char dsm[];
    __shared__ float s_bias[COn];

    const int t0 = blockIdx.x * TILE_M;
    const int f  = blockIdx.y;
    const int b  = blockIdx.z;
    const int tid = threadIdx.x;
    const int wid = tid >> 5;
    const int lane = tid & 31;
    const int wm = (wid >> 1) * 32;      // warp M base (0,32,64,96)
    const int wn = (wid & 1) * 64;       // warp N base (0,64)

    const uint32_t smb = smem_u32(dsm);

    const float* xb = x + ((long long)b * Tn * Fn + f) * CIn;   // + t*4096 + ci
    const float* wf = g_wB + (long long)f * Kn * COn * CIn;     // + tap*16384 + o*128 + ci

    if (tid < COn) s_bias[tid] = bias[f * COn + tid];

    // ---- loader: chunk c -> stage s (4 A + 4 B float4s per thread) ----
    const int lrow32 = tid >> 3;         // 0..31
    const int lcol   = tid & 7;          // 16B column within 128B row
    auto load_chunk = [&](int c, int s) {
        const int ktap = c >> 2;
        const int ci0  = (c & 3) * CHUNK;
        const int tshift = -DILn * (Kn - 1) + DILn * ktap;      // -4,-2,0
        const uint32_t Ab = smb + s * STAGE_BYTES;
        const uint32_t Bb = Ab + 16384;
        #pragma unroll
        for (int p = 0; p < 4; p++) {
            const int row = p * 32 + lrow32;
            // A
            const int tg = t0 + row + tshift;
            const float* ga = (tg >= 0) ? xb + (long long)tg * (Fn * CIn) + ci0 + lcol * 4
                                        : xb;
            cp16(Ab + SWZ128(row * 128 + lcol * 16), ga, (tg >= 0) ? 16u : 0u);
            // B
            const float* gb = wf + (long long)ktap * (COn * CIn) + (long long)row * CIn
                              + ci0 + lcol * 4;
            cp16(Bb + SWZ128(row * 128 + lcol * 16), gb, 16u);
        }
    };

    // ---- prologue ----
    load_chunk(0, 0);
    asm volatile("cp.async.commit_group;");

    __syncthreads();   // s_bias ready

    // ---- accumulators (init with bias) ----
    float acc[2][8][4];
    #pragma unroll
    for (int nf = 0; nf < 8; nf++) {
        const int n = wn + nf * 8 + (lane & 3) * 2;
        const float b0 = s_bias[n], b1 = s_bias[n + 1];
        #pragma unroll
        for (int mf = 0; mf < 2; mf++) {
            acc[mf][nf][0] = b0; acc[mf][nf][1] = b1;
            acc[mf][nf][2] = b0; acc[mf][nf][3] = b1;
        }
    }

    // ldmatrix lane addressing
    const int a_row = wm + (lane & 15);
    const int a_cb  = (lane >> 4) << 4;                  // 0 or 16
    const int b_row = wn + (lane & 7) + ((lane >> 4) << 3);
    const int b_cb  = ((lane >> 3) & 1) * 16;

    // ---- main loop (2-stage double buffer) ----
    #pragma unroll 1
    for (int c = 0; c < NCHUNKS; c++) {
        const int s = c & 1;
        asm volatile("cp.async.wait_group 0;");
        __syncthreads();

        if (c + 1 < NCHUNKS) {
            load_chunk(c + 1, s ^ 1);
            asm volatile("cp.async.commit_group;");
        }

        const uint32_t Ab = smb + s * STAGE_BYTES;
        const uint32_t Bb = Ab + 16384;

        #pragma unroll
        for (int ks = 0; ks < 4; ks++) {
            uint32_t afr[2][4], bfr[8][2];
            #pragma unroll
            for (int mf = 0; mf < 2; mf++)
                ldsm_x4(afr[mf][0], afr[mf][1], afr[mf][2], afr[mf][3],
                        Ab + SWZ128((a_row + mf * 16) * 128 + ks * 32 + a_cb));
            #pragma unroll
            for (int nf2 = 0; nf2 < 4; nf2++) {
                uint32_t r0, r1, r2, r3;
                ldsm_x4(r0, r1, r2, r3,
                        Bb + SWZ128((b_row + nf2 * 16) * 128 + ks * 32 + b_cb));
                bfr[nf2 * 2][0] = r0;     bfr[nf2 * 2][1] = r1;
                bfr[nf2 * 2 + 1][0] = r2; bfr[nf2 * 2 + 1][1] = r3;
            }
            #pragma unroll
            for (int mf = 0; mf < 2; mf++)
                #pragma unroll
                for (int nf = 0; nf < 8; nf++)
                    mma_tf32(acc[mf][nf], afr[mf], bfr[nf]);
        }
    }

    // ---- epilogue ----
    #pragma unroll
    for (int mf = 0; mf < 2; mf++) {
        #pragma unroll
        for (int r2 = 0; r2 < 2; r2++) {
            const int t = t0 + wm + mf * 16 + (lane >> 2) + r2 * 8;
            float* yrow = y + ((long long)(b * Tn + t) * Fn + f) * COn;
            #pragma unroll
            for (int nf = 0; nf < 8; nf++) {
                const int n = wn + nf * 8 + (lane & 3) * 2;
                float2 v = make_float2(acc[mf][nf][r2 * 2], acc[mf][nf][r2 * 2 + 1]);
                *reinterpret_cast<float2*>(yrow + n) = v;
            }
        }
    }
}

// ---------------------------------------------------------------------------
extern "C" void kernel_launch(void* const* d_in, const int* in_sizes, int n_in,
                              void* d_out, int out_size) {
    const float* x    = (const float*)d_in[0];  // [B, T, F, CI]
    const float* w    = (const float*)d_in[1];  // [F, CO, CI, K]
    const float* bias = (const float*)d_in[2];  // [F, CO]
    float* y = (float*)d_out;                   // [B, T, F, CO]
    (void)in_sizes; (void)n_in; (void)out_size;

    {
        const int total = Fn * Kn * COn * CIn;
        prep_w<<<(total + 255) / 256, 256>>>(w);
    }
    {
        static bool attr_set = false;
        if (!attr_set) {
            cudaFuncSetAttribute(conv_mma_kernel,
                                 cudaFuncAttributeMaxDynamicSharedMemorySize, DYN_SMEM);
            attr_set = true;
        }
        dim3 grid(Tn / TILE_M, Fn, Bn);   // (4, 32, 16) = 2048 CTAs
        conv_mma_kernel<<<grid, NTHREADS, DYN_SMEM>>>(x, bias, y);
    }
}